// round 11
// baseline (speedup 1.0000x reference)
#include <cuda_runtime.h>
#include <cstdint>

#define B_ 256
#define T_ 1024
#define D_ 64
#define H_ 100
#define G_ 400   // 4*H

// Precomputed input-gate contributions (bias included), row-major:
// xg[b][t][row], row = gate*H + j  (matches R1 lstm).  ~419 MB.
__device__ float g_xg[(size_t)B_ * T_ * G_];

// ---------------------------------------------------------------------------
// Packed f32x2 helpers
// ---------------------------------------------------------------------------
__device__ __forceinline__ unsigned long long ffma2(unsigned long long a,
                                                    unsigned long long b,
                                                    unsigned long long c) {
    unsigned long long d;
    asm("fma.rn.f32x2 %0, %1, %2, %3;" : "=l"(d) : "l"(a), "l"(b), "l"(c));
    return d;
}
__device__ __forceinline__ unsigned long long pack2(float x, float y) {
    return ((unsigned long long)__float_as_uint(y) << 32) |
           (unsigned long long)__float_as_uint(x);
}
__device__ __forceinline__ float lo2(unsigned long long v) {
    return __uint_as_float((unsigned)v);
}
__device__ __forceinline__ float hi2(unsigned long long v) {
    return __uint_as_float((unsigned)(v >> 32));
}
__device__ __forceinline__ float sig_f(float x) {
    return __fdividef(1.0f, 1.0f + __expf(-x));
}
__device__ __forceinline__ float tanh_f(float x) {
    return 1.0f - __fdividef(2.0f, __expf(2.0f * x) + 1.0f);
}

// ---------------------------------------------------------------------------
// Kernel 1 (v4, split-k): xg[b,t,row] = x[b,t,:] . W_ih[row,:] + bias[row]
// Thread = (row r, k-quarter q): 8 packed weight pairs in 16 regs.
// Per t: 4 LDS.128 + 8 FFMA2 + 2 shfl_xor butterfly; q==0 lane stores.
// 800 threads cover 200 rows; blockIdx.z picks the row half.
// Reg-lean (~40) -> 2 blocks/SM -> 50 warps of latency coverage.
// ---------------------------------------------------------------------------
__global__ __launch_bounds__(800, 2)
void xg_kernel(const float* __restrict__ x,
               const float* __restrict__ W_ih,
               const float* __restrict__ b_ih,
               const float* __restrict__ b_hh) {
    __shared__ ulonglong2 xs[64][16];   // 64 t x 64 k fp32 tile (16 KB)

    const int b   = blockIdx.y;
    const int t0  = blockIdx.x * 64;
    const int tid = threadIdx.x;
    const int q   = tid & 3;            // k-quarter: pairs [8q, 8q+8)
    const int r   = tid >> 2;           // local row 0..199
    const int row = blockIdx.z * 200 + r;

    {   // coalesced float4 tile load (1024 chunks / 800 threads)
        const float4* src = (const float4*)(x + ((size_t)b * T_ + t0) * D_);
        float4* dst = (float4*)xs;
        for (int i = tid; i < 64 * 16; i += 800) dst[i] = src[i];
    }

    // weights: k-pairs [8q, 8q+8) of W_ih row
    unsigned long long w2[8];
    {
        const float4* wr = (const float4*)(W_ih + (size_t)row * D_ + q * 16);
#pragma unroll
        for (int m = 0; m < 4; m++) {
            float4 v = wr[m];
            w2[2 * m]     = pack2(v.x, v.y);
            w2[2 * m + 1] = pack2(v.z, v.w);
        }
    }
    const float bias = b_ih[row] + b_hh[row];
    __syncthreads();

    float* outp = g_xg + ((size_t)b * T_ + t0) * G_ + row;
    for (int t = 0; t < 64; t += 2) {
        unsigned long long a0 = 0ull, a1 = 0ull;
#pragma unroll
        for (int i = 0; i < 4; i++) {
            ulonglong2 xv = xs[t][4 * q + i];       // 4 addrs/warp, no conflict
            ulonglong2 xw = xs[t + 1][4 * q + i];
            a0 = ffma2(w2[2 * i],     xv.x, a0);
            a0 = ffma2(w2[2 * i + 1], xv.y, a0);
            a1 = ffma2(w2[2 * i],     xw.x, a1);
            a1 = ffma2(w2[2 * i + 1], xw.y, a1);
        }
        float p0 = lo2(a0) + hi2(a0);
        float p1 = lo2(a1) + hi2(a1);
        // butterfly over the 4 q-lanes: full dot product in every lane
        p0 += __shfl_xor_sync(0xffffffffu, p0, 1);
        p1 += __shfl_xor_sync(0xffffffffu, p1, 1);
        p0 += __shfl_xor_sync(0xffffffffu, p0, 2);
        p1 += __shfl_xor_sync(0xffffffffu, p1, 2);
        if (q == 0) {                   // 8 lanes/warp -> 32B contiguous
            outp[(size_t)t * G_]       = p0 + bias;
            outp[(size_t)(t + 1) * G_] = p1 + bias;
        }
    }
}

// ---------------------------------------------------------------------------
// Kernel 2: recurrence — R1 version verbatim (best measured).
// 128 blocks x 2 batch rows, 416 threads; thread tid<400 owns W_hh row tid
// (50 packed f32x2 regs), h in shared ulonglong2, gbuf 2-phase, 2 barriers.
// ---------------------------------------------------------------------------
__global__ __launch_bounds__(416, 1)
void lstm_kernel(const float* __restrict__ h0,
                 const float* __restrict__ c0,
                 const float* __restrict__ W_hh,
                 const float* __restrict__ W_fc,
                 const float* __restrict__ b_fc,
                 float* __restrict__ out) {
    __shared__ ulonglong2 hs[2][25];     // 2 x 100 floats (h per batch row)
    __shared__ float gbuf[2][G_];        // activated gates
    __shared__ float wfc_s[H_];

    const int tid    = threadIdx.x;
    const int batch0 = blockIdx.x * 2;

    float c = 0.0f;
    if (tid < 2 * H_) {
        const int b = tid / H_, j = tid - b * H_;
        ((float*)hs[b])[j] = h0[(size_t)(batch0 + b) * H_ + j];
        c = c0[(size_t)(batch0 + b) * H_ + j];
    }
    if (tid < H_) wfc_s[tid] = W_fc[tid];

    unsigned long long w2[50];
    if (tid < G_) {
        const float4* wrow = (const float4*)(W_hh + (size_t)tid * H_);
#pragma unroll
        for (int i = 0; i < 25; i++) {
            float4 v = wrow[i];
            w2[2 * i]     = pack2(v.x, v.y);
            w2[2 * i + 1] = pack2(v.z, v.w);
        }
    }

    const float* xg0 = g_xg + (size_t)(batch0)     * T_ * G_ + tid;
    const float* xg1 = g_xg + (size_t)(batch0 + 1) * T_ * G_ + tid;
    float xgc0 = 0.0f, xgc1 = 0.0f;
    if (tid < G_) { xgc0 = xg0[0]; xgc1 = xg1[0]; }

    __syncthreads();

    for (int t = 0; t < T_; t++) {
        float xgn0 = 0.0f, xgn1 = 0.0f;
        if (tid < G_ && t + 1 < T_) {
            xgn0 = xg0[(size_t)(t + 1) * G_];
            xgn1 = xg1[(size_t)(t + 1) * G_];
        }

        if (tid < G_) {
            unsigned long long a0 = 0ull, a1 = 0ull, b0 = 0ull, b1 = 0ull;
#pragma unroll
            for (int i = 0; i < 25; i++) {
                ulonglong2 hv = hs[0][i];
                a0 = ffma2(w2[2 * i],     hv.x, a0);
                a1 = ffma2(w2[2 * i + 1], hv.y, a1);
            }
#pragma unroll
            for (int i = 0; i < 25; i++) {
                ulonglong2 hv = hs[1][i];
                b0 = ffma2(w2[2 * i],     hv.x, b0);
                b1 = ffma2(w2[2 * i + 1], hv.y, b1);
            }
            float acc0 = lo2(a0) + hi2(a0) + lo2(a1) + hi2(a1) + xgc0;
            float acc1 = lo2(b0) + hi2(b0) + lo2(b1) + hi2(b1) + xgc1;

            float r0, r1;
            if (tid >= 200 && tid < 300) {         // cell gate g -> tanh
                r0 = tanh_f(acc0);
                r1 = tanh_f(acc1);
            } else {                               // i, f, o -> sigmoid
                r0 = sig_f(acc0);
                r1 = sig_f(acc1);
            }
            gbuf[0][tid] = r0;
            gbuf[1][tid] = r1;
        }
        __syncthreads();

        if (tid < 2 * H_) {
            const int b = tid / H_, j = tid - b * H_;
            float iv = gbuf[b][j];
            float fv = gbuf[b][H_ + j];
            float gv = gbuf[b][2 * H_ + j];
            float ov = gbuf[b][3 * H_ + j];
            c = fv * c + iv * gv;
            ((float*)hs[b])[j] = ov * tanh_f(c);
        }
        xgc0 = xgn0;
        xgc1 = xgn1;
        __syncthreads();
    }

    if (tid < 2) {
        float acc = b_fc[0];
        const float* hp = (const float*)hs[tid];
#pragma unroll 4
        for (int j = 0; j < H_; j++) acc += hp[j] * wfc_s[j];
        out[batch0 + tid] = acc;
    }
}

// ---------------------------------------------------------------------------
extern "C" void kernel_launch(void* const* d_in, const int* in_sizes, int n_in,
                              void* d_out, int out_size) {
    const float* x    = (const float*)d_in[0];
    const float* h0   = (const float*)d_in[1];
    const float* c0   = (const float*)d_in[2];
    const float* W_ih = (const float*)d_in[3];
    const float* W_hh = (const float*)d_in[4];
    const float* b_ih = (const float*)d_in[5];
    const float* b_hh = (const float*)d_in[6];
    const float* W_fc = (const float*)d_in[7];
    const float* b_fc = (const float*)d_in[8];
    float* out = (float*)d_out;

    dim3 grid1(T_ / 64, B_, 2);
    xg_kernel<<<grid1, 800>>>(x, W_ih, b_ih, b_hh);

    lstm_kernel<<<B_ / 2, 416>>>(h0, c0, W_hh, W_fc, b_fc, out);
}

// round 13
// speedup vs baseline: 1.6883x; 1.6883x over previous
#include <cuda_runtime.h>
#include <cstdint>

#define B_ 256
#define T_ 1024
#define D_ 64
#define H_ 100
#define G_ 400   // 4*H
#define TT 256   // t-tile per xg block (amortizes the W-register prologue)
#define L2E 1.44269504088896f

// Precomputed input-gate contributions, PERMUTED row order:
// xg[b][t][p] holds gate-row ((p&3)*H + (p>>2)), bias included.  ~419 MB.
__device__ float g_xg[(size_t)B_ * T_ * G_];

// ---------------------------------------------------------------------------
// Packed f32x2 helpers
// ---------------------------------------------------------------------------
__device__ __forceinline__ unsigned long long ffma2(unsigned long long a,
                                                    unsigned long long b,
                                                    unsigned long long c) {
    unsigned long long d;
    asm("fma.rn.f32x2 %0, %1, %2, %3;" : "=l"(d) : "l"(a), "l"(b), "l"(c));
    return d;
}
__device__ __forceinline__ unsigned long long add2(unsigned long long a,
                                                   unsigned long long b) {
    unsigned long long d;
    asm("add.rn.f32x2 %0, %1, %2;" : "=l"(d) : "l"(a), "l"(b));
    return d;
}
__device__ __forceinline__ unsigned long long pack2(float x, float y) {
    return ((unsigned long long)__float_as_uint(y) << 32) |
           (unsigned long long)__float_as_uint(x);
}
__device__ __forceinline__ float lo2(unsigned long long v) {
    return __uint_as_float((unsigned)v);
}
__device__ __forceinline__ float hi2(unsigned long long v) {
    return __uint_as_float((unsigned)(v >> 32));
}
__device__ __forceinline__ float ex2a(float x) {
    float r; asm("ex2.approx.ftz.f32 %0, %1;" : "=f"(r) : "f"(x)); return r;
}
__device__ __forceinline__ float rcpa(float x) {
    float r; asm("rcp.approx.ftz.f32 %0, %1;" : "=f"(r) : "f"(x)); return r;
}
// sigmoid(x) = 1 - 1/(e^x+1)  (lm=log2e, s=1);  tanh(x) = 1 - 2/(e^2x+1)
__device__ __forceinline__ float uact(float x, float lm, float s) {
    return 1.0f - s * rcpa(ex2a(lm * x) + 1.0f);
}
__device__ __forceinline__ float tanh_f(float x) {
    return 1.0f - __fdividef(2.0f, __expf(2.0f * x) + 1.0f);
}

// ---------------------------------------------------------------------------
// Kernel 1: xg[b,t,p] = x[b,t,:] . W_ih[row,:] + (b_ih+b_hh)[row],
//           row = (p&3)*H + (p>>2)  (quad-permuted for the lstm kernel).
// R1 structure EXACTLY, but t-tile = 256 (dynamic 64KB smem) so the
// W-into-registers prologue is paid 4x less often. Grid (4, 256).
// ---------------------------------------------------------------------------
__global__ __launch_bounds__(512, 1)
void xg_kernel(const float* __restrict__ x,
               const float* __restrict__ W_ih,
               const float* __restrict__ b_ih,
               const float* __restrict__ b_hh) {
    extern __shared__ ulonglong2 xs[];  // [TT][16] : 256 t x 64 k fp32 (64 KB)

    const int b   = blockIdx.y;
    const int t0  = blockIdx.x * TT;
    const int tid = threadIdx.x;

    {   // coalesced float4 tile load: TT*16 = 4096 chunks / 512 threads
        const float4* src = (const float4*)(x + ((size_t)b * T_ + t0) * D_);
        float4* dst = (float4*)xs;
#pragma unroll
        for (int it = 0; it < TT * 16 / 512; it++)
            dst[tid + it * 512] = src[tid + it * 512];
    }

    unsigned long long w2[32];
    float bias = 0.0f;
    if (tid < G_) {
        const int row = (tid & 3) * H_ + (tid >> 2);
        const float4* wrow = (const float4*)(W_ih + (size_t)row * D_);
#pragma unroll
        for (int i = 0; i < 16; i++) {
            float4 v = wrow[i];
            w2[2 * i]     = pack2(v.x, v.y);
            w2[2 * i + 1] = pack2(v.z, v.w);
        }
        bias = b_ih[row] + b_hh[row];
    }
    __syncthreads();

    if (tid < G_) {
        float* out = g_xg + ((size_t)b * T_ + t0) * G_ + tid;
#pragma unroll 2
        for (int t = 0; t < TT; t++) {
            unsigned long long a0 = 0ull, a1 = 0ull;
#pragma unroll
            for (int i = 0; i < 16; i++) {
                ulonglong2 xv = xs[t * 16 + i];    // broadcast LDS.128
                a0 = ffma2(w2[2 * i],     xv.x, a0);
                a1 = ffma2(w2[2 * i + 1], xv.y, a1);
            }
            unsigned long long s2 = add2(a0, a1);
            out[(size_t)t * G_] = lo2(s2) + hi2(s2) + bias;
        }
    }
}

// ---------------------------------------------------------------------------
// Kernel 2: recurrence — R1 structure (best measured ~1.11 ms), with
// branch-free uniform activation and single-LDS.128 phase B (quad-permuted
// gate rows). 128 blocks x 2 batch rows, 416 threads; thread tid<400 owns
// W_hh row ((tid&3)*H + (tid>>2)) in 50 packed f32x2 regs; 2 barriers/step.
// ---------------------------------------------------------------------------
__global__ __launch_bounds__(416, 1)
void lstm_kernel(const float* __restrict__ h0,
                 const float* __restrict__ c0,
                 const float* __restrict__ W_hh,
                 const float* __restrict__ W_fc,
                 const float* __restrict__ b_fc,
                 float* __restrict__ out) {
    __shared__ ulonglong2 hs[2][25];     // 2 x 100 floats (h per batch row)
    __shared__ float gbuf[2][G_];        // activated gates (permuted rows)
    __shared__ float wfc_s[H_];

    const int tid    = threadIdx.x;
    const int batch0 = blockIdx.x * 2;

    float c = 0.0f;
    if (tid < 2 * H_) {
        const int b = tid / H_, j = tid - b * H_;
        ((float*)hs[b])[j] = h0[(size_t)(batch0 + b) * H_ + j];
        c = c0[(size_t)(batch0 + b) * H_ + j];
    }
    if (tid < H_) wfc_s[tid] = W_fc[tid];

    unsigned long long w2[50];
    float lm = L2E, sc = 1.0f;           // sigmoid consts
    if (tid < G_) {
        const int gate = tid & 3;
        const int row  = gate * H_ + (tid >> 2);
        const float4* wrow = (const float4*)(W_hh + (size_t)row * H_);
#pragma unroll
        for (int i = 0; i < 25; i++) {
            float4 v = wrow[i];
            w2[2 * i]     = pack2(v.x, v.y);
            w2[2 * i + 1] = pack2(v.z, v.w);
        }
        if (gate == 2) { lm = 2.0f * L2E; sc = 2.0f; }
    }

    const float* xg0 = g_xg + (size_t)(batch0)     * T_ * G_ + tid;
    const float* xg1 = g_xg + (size_t)(batch0 + 1) * T_ * G_ + tid;
    float xgc0 = 0.0f, xgc1 = 0.0f;
    if (tid < G_) { xgc0 = xg0[0]; xgc1 = xg1[0]; }

    __syncthreads();

    for (int t = 0; t < T_; t++) {
        float xgn0 = 0.0f, xgn1 = 0.0f;
        if (tid < G_ && t + 1 < T_) {
            xgn0 = xg0[(size_t)(t + 1) * G_];
            xgn1 = xg1[(size_t)(t + 1) * G_];
        }

        if (tid < G_) {
            unsigned long long a0 = 0ull, a1 = 0ull, b0 = 0ull, b1 = 0ull;
#pragma unroll
            for (int i = 0; i < 25; i++) {
                ulonglong2 hv = hs[0][i];          // broadcast LDS.128
                a0 = ffma2(w2[2 * i],     hv.x, a0);
                a1 = ffma2(w2[2 * i + 1], hv.y, a1);
            }
#pragma unroll
            for (int i = 0; i < 25; i++) {
                ulonglong2 hv = hs[1][i];
                b0 = ffma2(w2[2 * i],     hv.x, b0);
                b1 = ffma2(w2[2 * i + 1], hv.y, b1);
            }
            float acc0 = lo2(a0) + hi2(a0) + lo2(a1) + hi2(a1) + xgc0;
            float acc1 = lo2(b0) + hi2(b0) + lo2(b1) + hi2(b1) + xgc1;

            // branch-free uniform activation (sigmoid / tanh via consts)
            gbuf[0][tid] = uact(acc0, lm, sc);
            gbuf[1][tid] = uact(acc1, lm, sc);
        }
        __syncthreads();

        // phase B: gates of unit j are at gbuf[b][4j..4j+3] = one LDS.128
        if (tid < 2 * H_) {
            const int b = tid / H_, j = tid - b * H_;
            float4 g4 = *(const float4*)&gbuf[b][4 * j];   // {i,f,g,o}
            c = g4.y * c + g4.x * g4.z;
            ((float*)hs[b])[j] = g4.w * tanh_f(c);
        }
        xgc0 = xgn0;
        xgc1 = xgn1;
        __syncthreads();
    }

    if (tid < 2) {
        float acc = b_fc[0];
        const float* hp = (const float*)hs[tid];
#pragma unroll 4
        for (int j = 0; j < H_; j++) acc += hp[j] * wfc_s[j];
        out[batch0 + tid] = acc;
    }
}

// ---------------------------------------------------------------------------
extern "C" void kernel_launch(void* const* d_in, const int* in_sizes, int n_in,
                              void* d_out, int out_size) {
    const float* x    = (const float*)d_in[0];
    const float* h0   = (const float*)d_in[1];
    const float* c0   = (const float*)d_in[2];
    const float* W_ih = (const float*)d_in[3];
    const float* W_hh = (const float*)d_in[4];
    const float* b_ih = (const float*)d_in[5];
    const float* b_hh = (const float*)d_in[6];
    const float* W_fc = (const float*)d_in[7];
    const float* b_fc = (const float*)d_in[8];
    float* out = (float*)d_out;

    static int smem_set = 0;
    if (!smem_set) {   // host-side, idempotent attribute set (not captured)
        cudaFuncSetAttribute(xg_kernel,
                             cudaFuncAttributeMaxDynamicSharedMemorySize,
                             TT * 16 * (int)sizeof(ulonglong2));
        smem_set = 1;
    }

    dim3 grid1(T_ / TT, B_);
    xg_kernel<<<grid1, 512, TT * 16 * sizeof(ulonglong2)>>>(x, W_ih, b_ih, b_hh);

    lstm_kernel<<<B_ / 2, 416>>>(h0, c0, W_hh, W_fc, b_fc, out);
}